// round 15
// baseline (speedup 1.0000x reference)
#include <cuda_runtime.h>
#include <math.h>
#include <stdint.h>

#define T_STEPS 16
#define BATCH   64
#define DG      512
#define DH      1024
#define DOUT    512
#define S_STEPS 3
#define LAMBDA  0.95f
#define ETA     0.5f

#define NBLK 64
#define NTHR 1024
#define ASTRIDE 516                       // 516 mod 32 = 4 -> conflict-free frag gather
#define DYN_SMEM (64 * ASTRIDE * 4)       // 132096 B

// ---------------- device scratch ----------------
__device__ float g_h[BATCH * DH];
__device__ float g_hbase[BATCH * DH];     // h @ W_h^T (full K, no partials)
__device__ float g_zwg[T_STEPS * BATCH * DH];
__device__ float g_hist[T_STEPS - 1][BATCH * DH];
__device__ float g_gram[BATCH * 256];
__device__ float g_hsum[BATCH * 16];
__device__ float g_pred[BATCH * DOUT];
__device__ float g_lossb[BATCH];
__device__ float g_accb[BATCH];

// pre-packed tf32 hi/lo B-fragments
__device__ float g_whf_hi[DH * DH];
__device__ float g_whf_lo[DH * DH];
__device__ float g_wgf_hi[DH * DG];
__device__ float g_wgf_lo[DH * DG];
__device__ float g_hwf_hi[DOUT * DH];
__device__ float g_hwf_lo[DOUT * DH];

// grid barrier
__device__ unsigned g_bar_cnt = 0;
__device__ volatile unsigned g_bar_gen = 0;

__device__ __forceinline__ void bar_sync(unsigned& gen) {
    __syncthreads();
    if (threadIdx.x == 0) {
        __threadfence();
        unsigned t = atomicAdd(&g_bar_cnt, 1u);
        if (t == NBLK - 1) {
            g_bar_cnt = 0u;
            __threadfence();
            g_bar_gen = gen + 1u;
        } else {
            while (g_bar_gen == gen) { }
        }
    }
    __syncthreads();
    gen++;
}

// ---------------- tf32 helpers ----------------
__device__ __forceinline__ uint32_t f2tf32(float x) {
    uint32_t r;
    asm("cvt.rna.tf32.f32 %0, %1;" : "=r"(r) : "f"(x));
    return r;
}
__device__ __forceinline__ void mma8(float* c, uint4 a, uint32_t b0, uint32_t b1) {
    asm volatile(
        "mma.sync.aligned.m16n8k8.row.col.f32.tf32.tf32.f32 "
        "{%0,%1,%2,%3}, {%4,%5,%6,%7}, {%8,%9}, {%0,%1,%2,%3};"
        : "+f"(c[0]), "+f"(c[1]), "+f"(c[2]), "+f"(c[3])
        : "r"(a.x), "r"(a.y), "r"(a.z), "r"(a.w), "r"(b0), "r"(b1));
}

// ---------------- B-fragment prepack ----------------
__device__ void pack_w(const float* __restrict__ W, float* __restrict__ hi,
                       float* __restrict__ lo, int NK, int klog, int kfrag8) {
    const int kmask = (1 << klog) - 1;
    for (int idx = blockIdx.x * NTHR + threadIdx.x; idx < NK; idx += NBLK * NTHR) {
        int n = idx >> klog, k = idx & kmask;
        float v = W[idx];
        uint32_t hb = f2tf32(v);
        uint32_t lb = f2tf32(v - __uint_as_float(hb));
        int n8 = n >> 3, k8 = k >> 3;
        int lane = (n & 7) * 4 + (k & 3);
        int reg = (k >> 2) & 1;
        size_t a = ((size_t)(n8 * kfrag8 + k8) * 32 + lane) * 2 + reg;
        hi[a] = __uint_as_float(hb);
        lo[a] = __uint_as_float(lb);
    }
}

// ---------------- few-segment tf32x3 GEMM ----------------
// out[m 0..63][n8base*8 .. +NREP*64) over K = NCH*512.
// Per chunk: [stage 64x512 raw fp32 into smem] sync [full-k8 register loop] —
// no kd split, no partials. 32 warps = mw(4) x n8w(8).
template <int NREP, int NCH>
__device__ void gemm_smemA(const float* __restrict__ X, int ldx,
                           const float* __restrict__ Bhi,
                           const float* __restrict__ Blo,
                           int kfrag8, int n8base,
                           float* __restrict__ out, int ldo, float* As) {
    const int tid = threadIdx.x, warp = tid >> 5, lane = tid & 31;
    const int mw = warp >> 3, n8w = warp & 7;
    const int gid = lane >> 2, tig = lane & 3;
    const int srow = tid >> 4, sfq = tid & 15;

    float c[NREP][4];
#pragma unroll
    for (int r = 0; r < NREP; r++)
#pragma unroll
        for (int j = 0; j < 4; j++) c[r][j] = 0.f;

#pragma unroll 1
    for (int ch = 0; ch < NCH; ch++) {
        __syncthreads();
        {   // stage: 64 rows x 512 cols, coalesced float4, L2 (ldcg)
            const float4* src = (const float4*)(X + (size_t)srow * ldx + ch * 512);
#pragma unroll
            for (int j = 0; j < 8; j++) {
                float4 v = __ldcg(src + sfq + j * 16);
                *(float4*)&As[srow * ASTRIDE + (sfq + j * 16) * 4] = v;
            }
        }
        __syncthreads();
        const int r0 = (mw * 16 + gid) * ASTRIDE;
        const int r1 = r0 + 8 * ASTRIDE;
#pragma unroll 4
        for (int k8 = 0; k8 < 64; k8++) {
            const int col = k8 * 8 + tig;
            float a0 = As[r0 + col],     a1 = As[r1 + col];
            float a2 = As[r0 + col + 4], a3 = As[r1 + col + 4];
            uint32_t h0 = f2tf32(a0), h1 = f2tf32(a1);
            uint32_t h2 = f2tf32(a2), h3 = f2tf32(a3);
            uint4 ah = make_uint4(h0, h1, h2, h3);
            uint4 al = make_uint4(f2tf32(a0 - __uint_as_float(h0)),
                                  f2tf32(a1 - __uint_as_float(h1)),
                                  f2tf32(a2 - __uint_as_float(h2)),
                                  f2tf32(a3 - __uint_as_float(h3)));
            const int k8g = ch * 64 + k8;
#pragma unroll
            for (int rep = 0; rep < NREP; rep++) {
                const int n8g = n8base + rep * 8 + n8w;
                const size_t ba = ((size_t)(n8g * kfrag8 + k8g) * 32 + lane) * 2;
                float2 bh = *(const float2*)&Bhi[ba];
                float2 bl = *(const float2*)&Blo[ba];
                uint32_t bh0 = __float_as_uint(bh.x), bh1 = __float_as_uint(bh.y);
                mma8(c[rep], ah, bh0, bh1);
                mma8(c[rep], ah, __float_as_uint(bl.x), __float_as_uint(bl.y));
                mma8(c[rep], al, bh0, bh1);
            }
        }
    }

#pragma unroll
    for (int rep = 0; rep < NREP; rep++) {
        const int n = (n8base + rep * 8 + n8w) * 8 + tig * 2;
        const int m = mw * 16 + gid;
        *(float2*)&out[(size_t)m * ldo + n] = make_float2(c[rep][0], c[rep][1]);
        *(float2*)&out[(size_t)(m + 8) * ldo + n] = make_float2(c[rep][2], c[rep][3]);
    }
}

// ---------------- reductions (1024 threads, 32 warps) --------------------
__device__ __forceinline__ float wred(float s) {
#pragma unroll
    for (int o = 16; o > 0; o >>= 1) s += __shfl_down_sync(0xffffffffu, s, o);
    return s;
}
__device__ __forceinline__ void stage2(int nv, float* bc, float (*red)[21]) {
    const int lane = threadIdx.x & 31, warp = threadIdx.x >> 5;
    __syncthreads();
    if (warp < nv) {
        float s = wred(red[lane][warp]);
        if (lane == 0) bc[warp] = s;
    }
    __syncthreads();
}

// ---------------- refine phase (block = batch element, runtime t) -------
__device__ void refine_phase(int b, int t, bool last,
                             const float* __restrict__ b_h,
                             const float* __restrict__ gam,
                             const float* __restrict__ bet,
                             const float* __restrict__ alp) {
    const int i = threadIdx.x, lane = i & 31, warp = i >> 5;

    __shared__ float red[32][21];
    __shared__ float bcS[20];
    __shared__ float bc0[20];
    __shared__ float Gs[256];
    __shared__ float hsums[16];
    __shared__ float es[16];
    __shared__ float coef[4];

    const float g0 = gam[i], be0 = bet[i];

    float hb = b_h[i] + __ldcg(&g_zwg[((size_t)t * BATCH + b) * DH + i]);
    if (t > 0) hb += __ldcg(&g_hbase[(size_t)b * DH + i]);

    float hv[15];
#pragma unroll
    for (int tau = 0; tau < 15; tau++) {
        if (tau >= t) break;
        hv[tau] = g_hist[tau][b * DH + i];
    }

    if (i < 256) Gs[i] = g_gram[b * 256 + i];
    if (i < 16)  hsums[i] = g_hsum[b * 16 + i];

#pragma unroll
    for (int x = 0; x < 15; x++) {
        if (x >= t) break;
        float s = wred(hv[x] * hb);
        if (lane == 0) red[warp][x] = s;
    }
    {
        float s = wred(hb);
        if (lane == 0) red[warp][t] = s;
        s = wred(hb * hb);
        if (lane == 0) red[warp][t + 1] = s;
    }
    stage2(t + 2, bc0, red);

    float mu = bc0[t] * (1.f / DH);
    float var = bc0[t + 1] * (1.f / DH) - mu * mu;
    float rstd = rsqrtf(var + 1e-5f);
    float h = fmaxf((hb - mu) * rstd * g0 + be0, 0.f);

    const float alpha = *alp;
    float wdl = 0.f;
    if (warp == 0 && lane < t)
        wdl = ETA * powf(LAMBDA, (float)(t - 1 - lane));

    for (int s = 0; s < S_STEPS; s++) {
#pragma unroll
        for (int x = 0; x < 15; x++) {
            if (x >= t) break;
            float v = wred(hv[x] * h);
            if (lane == 0) red[warp][x] = v;
        }
        {
            float v = wred(h * h);
            if (lane == 0) red[warp][t] = v;
        }
        stage2(t + 1, bcS, red);

        if (warp == 0) {
            float d = (lane < t) ? bcS[lane] : 0.f;
            float e = wdl * d;
            if (lane < 16) es[lane] = e;
            __syncwarp();
            float f = 0.f;
            if (lane < t) {
                for (int sg = 0; sg < t; sg++)
                    f += es[sg] * Gs[lane * 16 + sg];
            }
            float hbd = (lane < t) ? bc0[lane] : 0.f;
            float hsm = (lane < t) ? hsums[lane] : 0.f;
            float pA = e * d, pB = e * hbd, pC = e * hsm, pD = e * f;
#pragma unroll
            for (int o = 8; o > 0; o >>= 1) {
                pA += __shfl_down_sync(0xffffffffu, pA, o);
                pB += __shfl_down_sync(0xffffffffu, pB, o);
                pC += __shfl_down_sync(0xffffffffu, pC, o);
                pD += __shfl_down_sync(0xffffffffu, pD, o);
            }
            if (lane == 0) {
                float c1, c2;
                if (!last) {
                    float hh = bcS[t];
                    float n1 = sqrtf(hh) + 1e-6f;
                    float n2 = sqrtf(fmaxf(pD, 0.f)) + 1e-6f;
                    float R  = pA / (n1 * n2 + 1e-6f);
                    float Rp = fminf(fmaxf(R, 0.f), 1.f);
                    float spp = fmaxf(alpha, 0.f) + log1pf(expf(-fabsf(alpha)));
                    float spn = fmaxf(-alpha, 0.f) + log1pf(expf(-fabsf(alpha)));
                    float kco = (alpha >= 0.f) ? (1.f + spp) : (1.f / (1.f + spn));
                    float a   = 1.f - powf(1.f - Rp, kco);
                    c1 = 1.f - a * a;
                    c2 = a;
                } else {
                    c1 = 1.f;
                    c2 = 1.f;
                }
                float sum_hn  = c1 * bc0[t] + c2 * pC;
                float sum_hn2 = c1 * c1 * bc0[t + 1] + 2.f * c1 * c2 * pB +
                                c2 * c2 * pD;
                float mu_n  = sum_hn * (1.f / DH);
                float var_n = sum_hn2 * (1.f / DH) - mu_n * mu_n;
                coef[0] = c1; coef[1] = c2;
                coef[2] = mu_n; coef[3] = rsqrtf(var_n + 1e-5f);
            }
        }
        __syncthreads();

        float Ah = 0.f;
#pragma unroll
        for (int tau = 0; tau < 15; tau++) {
            if (tau >= t) break;
            Ah += es[tau] * hv[tau];
        }
        float hn = coef[0] * hb + coef[1] * Ah;
        h = fmaxf((hn - coef[2]) * coef[3] * g0 + be0, 0.f);
        __syncthreads();
    }

    g_h[b * DH + i] = h;

    if (!last) {
#pragma unroll
        for (int x = 0; x < 15; x++) {
            if (x >= t) break;
            float v = wred(hv[x] * h);
            if (lane == 0) red[warp][x] = v;
        }
        {
            float v = wred(h);
            if (lane == 0) red[warp][t] = v;
            v = wred(h * h);
            if (lane == 0) red[warp][t + 1] = v;
        }
        stage2(t + 2, bcS, red);
        if (i < t) {
            g_gram[b * 256 + t * 16 + i] = bcS[i];
            g_gram[b * 256 + i * 16 + t] = bcS[i];
        }
        if (i == 0) {
            g_gram[b * 256 + t * 16 + t] = bcS[t + 1];
            g_hsum[b * 16 + t] = bcS[t];
        }
        g_hist[t][b * DH + i] = h;
    }
}

// ---------------- loss phase ----------------
__device__ void loss_phase(int b, const float* __restrict__ clean,
                           const float* __restrict__ head_b) {
    const int o = threadIdx.x, lane = o & 31, warp = o >> 5;
    __shared__ float red[32][21];
    __shared__ float bc[20];
    float v0 = 0.f, v1 = 0.f, v2 = 0.f, v3 = 0.f;
    if (o < DOUT) {
        float pred = __ldcg(&g_pred[(size_t)b * DOUT + o]) + head_b[o];
        float c = clean[b * DOUT + o];
        float d = pred - c;
        v0 = pred * c; v1 = pred * pred; v2 = c * c; v3 = d * d;
    }
    float s0 = wred(v0), s1 = wred(v1), s2 = wred(v2), s3 = wred(v3);
    if (lane == 0) {
        red[warp][0] = s0; red[warp][1] = s1;
        red[warp][2] = s2; red[warp][3] = s3;
    }
    stage2(4, bc, red);
    if (o == 0) {
        g_lossb[b] = bc[3] / (bc[2] + 1e-6f);
        g_accb[b]  = bc[0] / ((sqrtf(bc[1]) + 1e-6f) * (sqrtf(bc[2]) + 1e-6f));
    }
}

// ---------------- the one persistent kernel ----------------
__global__ void __launch_bounds__(NTHR, 1) fused_kernel(
    const float* __restrict__ z_seq, const float* __restrict__ clean,
    const float* __restrict__ W_h, const float* __restrict__ W_g,
    const float* __restrict__ b_h, const float* __restrict__ ln_g,
    const float* __restrict__ ln_b, const float* __restrict__ alpha,
    const float* __restrict__ head_W, const float* __restrict__ head_b,
    float* __restrict__ out) {
    extern __shared__ float As[];   // 132 KB dynamic A-stage buffer

    unsigned gen = g_bar_gen;
    const int bi = blockIdx.x;

    // phase 0: prepack weight fragments
    pack_w(W_h,    g_whf_hi, g_whf_lo, DH * DH,   10, DH / 8);
    pack_w(W_g,    g_wgf_hi, g_wgf_lo, DH * DG,    9, DG / 8);
    pack_w(head_W, g_hwf_hi, g_hwf_lo, DOUT * DH, 10, DH / 8);
    bar_sync(gen);

    // phase 1: zwg = z @ W_g^T (1024x1024x512): block = (mt 16, nq 4)
    {
        const int mt = bi >> 2, nq = bi & 3;
        gemm_smemA<4, 1>(z_seq + (size_t)mt * 64 * DG, DG,
                         g_wgf_hi, g_wgf_lo, DG / 8, nq * 32,
                         g_zwg + (size_t)mt * 64 * DH, DH, As);
    }
    bar_sync(gen);

    for (int t = 0; t < T_STEPS; t++) {
        if (t > 0) {
            if (bi < 16)   // 16 blocks x n64, full K=1024, no partials
                gemm_smemA<1, 2>(g_h, DH, g_whf_hi, g_whf_lo, DH / 8, bi * 8,
                                 g_hbase, DH, As);
            bar_sync(gen);
        }
        refine_phase(bi, t, t == T_STEPS - 1, b_h, ln_g, ln_b, alpha);
        bar_sync(gen);
    }

    if (bi < 8)            // head: 8 blocks x n64, full K
        gemm_smemA<1, 2>(g_h, DH, g_hwf_hi, g_hwf_lo, DH / 8, bi * 8,
                         g_pred, DOUT, As);
    bar_sync(gen);

    loss_phase(bi, clean, head_b);
    bar_sync(gen);

    if (bi == 0 && threadIdx.x < 32) {
        const int lane = threadIdx.x;
        float l = g_lossb[lane] + g_lossb[lane + 32];
        float a = g_accb[lane] + g_accb[lane + 32];
#pragma unroll
        for (int o = 16; o > 0; o >>= 1) {
            l += __shfl_down_sync(0xffffffffu, l, o);
            a += __shfl_down_sync(0xffffffffu, a, o);
        }
        if (lane == 0) {
            out[0] = l * (1.f / BATCH);
            out[1] = a * (1.f / BATCH);
        }
    }
}

// ---------------- launch ----------------
extern "C" void kernel_launch(void* const* d_in, const int* in_sizes, int n_in,
                              void* d_out, int out_size) {
    const float* z_seq  = (const float*)d_in[0];
    const float* clean  = (const float*)d_in[1];
    const float* W_h    = (const float*)d_in[2];
    const float* W_g    = (const float*)d_in[3];
    const float* b_h    = (const float*)d_in[4];
    const float* ln_g   = (const float*)d_in[5];
    const float* ln_b   = (const float*)d_in[6];
    const float* alpha  = (const float*)d_in[7];
    const float* head_W = (const float*)d_in[8];
    const float* head_b = (const float*)d_in[9];
    float* out = (float*)d_out;

    cudaFuncSetAttribute(fused_kernel,
                         cudaFuncAttributeMaxDynamicSharedMemorySize, DYN_SMEM);
    fused_kernel<<<NBLK, NTHR, DYN_SMEM>>>(z_seq, clean, W_h, W_g, b_h, ln_g,
                                           ln_b, alpha, head_W, head_b, out);
}

// round 16
// speedup vs baseline: 2.0174x; 2.0174x over previous
#include <cuda_runtime.h>
#include <math.h>
#include <stdint.h>

#define T_STEPS 16
#define BATCH   64
#define DG      512
#define DH      1024
#define DOUT    512
#define S_STEPS 3
#define LAMBDA  0.95f
#define ETA     0.5f

#define NBLK 128
#define NTHR 1024
#define KS   8            // k-splits for wh and head GEMMs

// ---------------- device scratch ----------------
__device__ float g_h[BATCH * DH];
__device__ float g_parts[KS][BATCH * DH];
__device__ float g_zwg[T_STEPS * BATCH * DH];
__device__ float g_hist[T_STEPS - 1][BATCH * DH];
__device__ float g_gram[BATCH * 256];
__device__ float g_hsum[BATCH * 16];
__device__ float g_hp[KS][BATCH * DOUT];
__device__ float g_lossb[BATCH];
__device__ float g_accb[BATCH];

// grid barrier
__device__ unsigned g_bar_cnt = 0;
__device__ volatile unsigned g_bar_gen = 0;

__device__ __forceinline__ void bar_sync(unsigned& gen) {
    __syncthreads();
    if (threadIdx.x == 0) {
        __threadfence();
        unsigned t = atomicAdd(&g_bar_cnt, 1u);
        if (t == NBLK - 1) {
            g_bar_cnt = 0u;
            __threadfence();
            g_bar_gen = gen + 1u;
        } else {
            while (g_bar_gen == gen) { }
        }
    }
    __syncthreads();
    gen++;
}

// ---------------- tf32 helpers ----------------
__device__ __forceinline__ uint32_t f2tf32(float x) {
    uint32_t r;
    asm("cvt.rna.tf32.f32 %0, %1;" : "=r"(r) : "f"(x));
    return r;
}
__device__ __forceinline__ void mma8(float* c, uint4 a, uint32_t b0, uint32_t b1) {
    asm volatile(
        "mma.sync.aligned.m16n8k8.row.col.f32.tf32.tf32.f32 "
        "{%0,%1,%2,%3}, {%4,%5,%6,%7}, {%8,%9}, {%0,%1,%2,%3};"
        : "+f"(c[0]), "+f"(c[1]), "+f"(c[2]), "+f"(c[3])
        : "r"(a.x), "r"(a.y), "r"(a.z), "r"(a.w), "r"(b0), "r"(b1));
}

// ---------------- A pack: stage 64 rows x 128 k chunk into smem frags ---
__device__ __forceinline__ void a_pack(uint32_t* Ah, uint32_t* Al,
                                       const float* __restrict__ X, int ldx,
                                       int koff) {
    const int tid = threadIdx.x;
    const int row = tid >> 4, q = tid & 15;
    const float4* p = (const float4*)(X + (size_t)row * ldx + koff + q * 8);
    float4 v0 = __ldcg(p), v1 = __ldcg(p + 1);
    float xv[8] = {v0.x, v0.y, v0.z, v0.w, v1.x, v1.y, v1.z, v1.w};
    const int mt = row >> 4, tr = row & 15;
#pragma unroll
    for (int c = 0; c < 8; c++) {
        int reg = (tr >= 8 ? 1 : 0) + (c >= 4 ? 2 : 0);
        int lane = (tr & 7) * 4 + (c & 3);
        int idx = ((q * 4 + mt) * 32 + lane) * 4 + reg;
        uint32_t hb = f2tf32(xv[c]);
        Ah[idx] = hb;
        Al[idx] = f2tf32(xv[c] - __uint_as_float(hb));
    }
}

// inline B-fragment from row-major W (L2)
__device__ __forceinline__ void bfrag(const float* __restrict__ W, int ldw,
                                      int n8g, int kg, int lane,
                                      uint32_t& bh0, uint32_t& bh1,
                                      uint32_t& bl0, uint32_t& bl1) {
    const float* p = W + (size_t)(n8g * 8 + (lane >> 2)) * ldw + kg + (lane & 3);
    float w0 = __ldg(p), w1 = __ldg(p + 4);
    bh0 = f2tf32(w0); bl0 = f2tf32(w0 - __uint_as_float(bh0));
    bh1 = f2tf32(w1); bl1 = f2tf32(w1 - __uint_as_float(bh1));
}

// ---------------- refine (block = batch element, runtime t) -------------
__device__ void refine_phase(int b, int t, bool last,
                             const float* __restrict__ b_h,
                             const float* __restrict__ gam,
                             const float* __restrict__ bet,
                             const float* __restrict__ alp) {
    const int i = threadIdx.x, lane = i & 31, warp = i >> 5;

    __shared__ float red[2][32][20];
    __shared__ float Gs[256];
    __shared__ float hsm[16];
    __shared__ float bc0s[20];
    __shared__ float es_s[16];
    __shared__ float coef[4];

    const float g0 = gam[i], be0 = bet[i];

    float hb = b_h[i] + __ldcg(&g_zwg[((size_t)t * BATCH + b) * DH + i]);
    if (t > 0) {
#pragma unroll
        for (int s = 0; s < KS; s++) hb += __ldcg(&g_parts[s][b * DH + i]);
    }

    float hv[15];
#pragma unroll
    for (int tau = 0; tau < 15; tau++) {
        if (tau >= t) break;
        hv[tau] = g_hist[tau][b * DH + i];
    }

    if (i < 256) Gs[i] = g_gram[b * 256 + i];
    if (i < 16)  hsm[i] = g_hsum[b * 16 + i];

    float wdl = 0.f;
    if (warp == 0 && lane < t)
        wdl = ETA * powf(LAMBDA, (float)(t - 1 - lane));

    // ---- init partials: hb.h_tau (t), sum hb, sum hb^2 ----
#pragma unroll
    for (int x = 0; x < 15; x++) {
        if (x >= t) break;
        float v = hv[x] * hb;
#pragma unroll
        for (int o = 16; o > 0; o >>= 1) v += __shfl_down_sync(~0u, v, o);
        if (lane == 0) red[0][warp][x] = v;
    }
    {
        float v = hb;
#pragma unroll
        for (int o = 16; o > 0; o >>= 1) v += __shfl_down_sync(~0u, v, o);
        if (lane == 0) red[0][warp][t] = v;
        v = hb * hb;
#pragma unroll
        for (int o = 16; o > 0; o >>= 1) v += __shfl_down_sync(~0u, v, o);
        if (lane == 0) red[0][warp][t + 1] = v;
    }
    __syncthreads();                                   // (1)
    if (warp == 0) {
        float s = 0.f;
        if (lane < t + 2) {
#pragma unroll 8
            for (int w = 0; w < 32; w++) s += red[0][w][lane];
            bc0s[lane] = s;
        }
        float bsum = __shfl_sync(~0u, s, t);
        float bsq  = __shfl_sync(~0u, s, t + 1);
        if (lane == 0) {
            float mu = bsum * (1.f / DH);
            float var = bsq * (1.f / DH) - mu * mu;
            coef[2] = mu;
            coef[3] = rsqrtf(var + 1e-5f);
        }
    }
    __syncthreads();                                   // (2)
    float h = fmaxf((hb - coef[2]) * coef[3] * g0 + be0, 0.f);

    const float alpha = *alp;

    for (int s = 0; s < S_STEPS; s++) {
        const int buf = (s + 1) & 1;
#pragma unroll
        for (int x = 0; x < 15; x++) {
            if (x >= t) break;
            float v = hv[x] * h;
#pragma unroll
            for (int o = 16; o > 0; o >>= 1) v += __shfl_down_sync(~0u, v, o);
            if (lane == 0) red[buf][warp][x] = v;
        }
        if (!last) {
            float v = h * h;
#pragma unroll
            for (int o = 16; o > 0; o >>= 1) v += __shfl_down_sync(~0u, v, o);
            if (lane == 0) red[buf][warp][t] = v;
        }
        __syncthreads();                               // per-step (a)

        if (warp == 0) {
            const int nv = t + (last ? 0 : 1);
            float d = 0.f;
            if (lane < nv) {
#pragma unroll 8
                for (int w = 0; w < 32; w++) d += red[buf][w][lane];
            }
            float e = (lane < t) ? wdl * d : 0.f;
            if (lane < 16) es_s[lane] = e;
            __syncwarp();
            float f = 0.f;
            if (lane < t) {
                for (int sg = 0; sg < t; sg++)
                    f += es_s[sg] * Gs[lane * 16 + sg];
            }
            float pA = e * d;
            float pB = (lane < t) ? e * bc0s[lane] : 0.f;
            float pC = (lane < t) ? e * hsm[lane] : 0.f;
            float pD = e * f;
#pragma unroll
            for (int o = 16; o > 0; o >>= 1) {
                pA += __shfl_down_sync(~0u, pA, o);
                pB += __shfl_down_sync(~0u, pB, o);
                pC += __shfl_down_sync(~0u, pC, o);
                pD += __shfl_down_sync(~0u, pD, o);
            }
            float hh = __shfl_sync(~0u, d, t);   // valid when !last
            if (lane == 0) {
                float c1, c2;
                if (!last) {
                    float n1 = sqrtf(hh) + 1e-6f;
                    float n2 = sqrtf(fmaxf(pD, 0.f)) + 1e-6f;
                    float R  = pA / (n1 * n2 + 1e-6f);
                    float Rp = fminf(fmaxf(R, 0.f), 1.f);
                    float spp = fmaxf(alpha, 0.f) + log1pf(expf(-fabsf(alpha)));
                    float spn = fmaxf(-alpha, 0.f) + log1pf(expf(-fabsf(alpha)));
                    float kco = (alpha >= 0.f) ? (1.f + spp) : (1.f / (1.f + spn));
                    float a   = 1.f - powf(1.f - Rp, kco);
                    c1 = 1.f - a * a;
                    c2 = a;
                } else {
                    c1 = 1.f;
                    c2 = 1.f;
                }
                float bsum = bc0s[t], bsq = bc0s[t + 1];
                float sum_hn  = c1 * bsum + c2 * pC;
                float sum_hn2 = c1 * c1 * bsq + 2.f * c1 * c2 * pB + c2 * c2 * pD;
                float mu_n  = sum_hn * (1.f / DH);
                float var_n = sum_hn2 * (1.f / DH) - mu_n * mu_n;
                coef[0] = c1;
                coef[1] = c2;
                coef[2] = mu_n;
                coef[3] = rsqrtf(var_n + 1e-5f);
            }
        }
        __syncthreads();                               // per-step (b)

        float Ah = 0.f;
#pragma unroll
        for (int tau = 0; tau < 15; tau++) {
            if (tau >= t) break;
            Ah += es_s[tau] * hv[tau];
        }
        float hn = coef[0] * hb + coef[1] * Ah;
        h = fmaxf((hn - coef[2]) * coef[3] * g0 + be0, 0.f);
    }

    g_h[b * DH + i] = h;

    if (!last) {
        g_hist[t][b * DH + i] = h;
        // append partials: h.h_tau (t), sum h, sum h^2
#pragma unroll
        for (int x = 0; x < 15; x++) {
            if (x >= t) break;
            float v = hv[x] * h;
#pragma unroll
            for (int o = 16; o > 0; o >>= 1) v += __shfl_down_sync(~0u, v, o);
            if (lane == 0) red[0][warp][x] = v;
        }
        {
            float v = h;
#pragma unroll
            for (int o = 16; o > 0; o >>= 1) v += __shfl_down_sync(~0u, v, o);
            if (lane == 0) red[0][warp][t] = v;
            v = h * h;
#pragma unroll
            for (int o = 16; o > 0; o >>= 1) v += __shfl_down_sync(~0u, v, o);
            if (lane == 0) red[0][warp][t + 1] = v;
        }
        __syncthreads();                               // (append)
        if (warp == 0 && lane < t + 2) {
            float s = 0.f;
#pragma unroll 8
            for (int w = 0; w < 32; w++) s += red[0][w][lane];
            if (lane < t) {
                g_gram[b * 256 + t * 16 + lane] = s;
                g_gram[b * 256 + lane * 16 + t] = s;
            } else if (lane == t) {
                g_hsum[b * 16 + t] = s;
            } else {
                g_gram[b * 256 + t * 16 + t] = s;
            }
        }
    }
}

// ---------------- the one persistent kernel ----------------
__global__ void __launch_bounds__(NTHR, 1) fused_kernel(
    const float* __restrict__ z_seq, const float* __restrict__ clean,
    const float* __restrict__ W_h, const float* __restrict__ W_g,
    const float* __restrict__ b_h, const float* __restrict__ ln_g,
    const float* __restrict__ ln_b, const float* __restrict__ alpha,
    const float* __restrict__ head_W, const float* __restrict__ head_b,
    float* __restrict__ out) {
    extern __shared__ __align__(16) uint32_t smem_u[];
    uint32_t* Ah = smem_u;                 // 8192 u32 (32 KB)
    uint32_t* Al = smem_u + 8192;
    uint32_t* Bh = smem_u + 16384;         // W_h slice frags, resident
    uint32_t* Bl = smem_u + 24576;

    __shared__ float red0[32][20];         // loss reduce
    __shared__ float bcL[4];

    unsigned gen = g_bar_gen;
    const int bi = blockIdx.x;
    const int tid = threadIdx.x, warp = tid >> 5, lane = tid & 31;
    const int mw = warp >> 3, n8w = warp & 7;
    const int gid = lane >> 2, tig = lane & 3;

    const int wh_nt = bi & 15, wh_ks = bi >> 4;    // wh tile: 16 nt x 8 ks

    // ---- pack resident W_h B-fragments (own smem, no barrier needed) ----
#pragma unroll
    for (int j = 0; j < 8; j++) {
        int e = tid + j * 1024;
        int n = e >> 7, k = e & 127;
        float v = W_h[(size_t)(wh_nt * 64 + n) * DH + wh_ks * 128 + k];
        uint32_t hb = f2tf32(v);
        int sidx = (((n >> 3) * 16 + (k >> 3)) * 32 + (n & 7) * 4 + (k & 3)) * 2 +
                   ((k >> 2) & 1);
        Bh[sidx] = hb;
        Bl[sidx] = f2tf32(v - __uint_as_float(hb));
    }

    // ---- zwg = z @ W_g^T (1024x1024x512): 16 mt x 8 nt8 = 128 blocks ----
    {
        const int mt = bi >> 3, nt8 = bi & 7;
        float c[2][4];
#pragma unroll
        for (int r = 0; r < 2; r++)
#pragma unroll
            for (int j = 0; j < 4; j++) c[r][j] = 0.f;
#pragma unroll 1
        for (int cc = 0; cc < 4; cc++) {
            __syncthreads();
            a_pack(Ah, Al, z_seq + (size_t)mt * 64 * DG, DG, cc * 128);
            __syncthreads();
#pragma unroll
            for (int k8 = 0; k8 < 16; k8++) {
                int ai = ((k8 * 4 + mw) * 32 + lane) * 4;
                uint4 ahf = *(const uint4*)&Ah[ai];
                uint4 alf = *(const uint4*)&Al[ai];
                int kg = cc * 128 + k8 * 8;
#pragma unroll
                for (int r = 0; r < 2; r++) {
                    int n8g = nt8 * 16 + n8w * 2 + r;
                    uint32_t bh0, bh1, bl0, bl1;
                    bfrag(W_g, DG, n8g, kg, lane, bh0, bh1, bl0, bl1);
                    mma8(c[r], ahf, bh0, bh1);
                    mma8(c[r], ahf, bl0, bl1);
                    mma8(c[r], alf, bh0, bh1);
                }
            }
        }
#pragma unroll
        for (int r = 0; r < 2; r++) {
            int n = (nt8 * 16 + n8w * 2 + r) * 8 + tig * 2;
            int m = mt * 64 + mw * 16 + gid;
            *(float2*)&g_zwg[(size_t)m * DH + n] = make_float2(c[r][0], c[r][1]);
            *(float2*)&g_zwg[(size_t)(m + 8) * DH + n] = make_float2(c[r][2], c[r][3]);
        }
    }
    bar_sync(gen);

    // ---- time loop ----
    for (int t = 0; t < T_STEPS; t++) {
        if (t > 0) {
            // wh GEMM: A chunk staged, B resident in smem. 2 sync segments.
            __syncthreads();
            a_pack(Ah, Al, g_h, DH, wh_ks * 128);
            __syncthreads();
            float c[4] = {0.f, 0.f, 0.f, 0.f};
#pragma unroll
            for (int k8 = 0; k8 < 16; k8++) {
                int ai = ((k8 * 4 + mw) * 32 + lane) * 4;
                uint4 ahf = *(const uint4*)&Ah[ai];
                uint4 alf = *(const uint4*)&Al[ai];
                int bi2 = ((n8w * 16 + k8) * 32 + lane) * 2;
                uint32_t bh0 = Bh[bi2], bh1 = Bh[bi2 + 1];
                uint32_t bl0 = Bl[bi2], bl1 = Bl[bi2 + 1];
                mma8(c, ahf, bh0, bh1);
                mma8(c, ahf, bl0, bl1);
                mma8(c, alf, bh0, bh1);
            }
            {
                int m = mw * 16 + gid;
                int n = wh_nt * 64 + n8w * 8 + tig * 2;
                float* o = g_parts[wh_ks];
                *(float2*)&o[(size_t)m * DH + n] = make_float2(c[0], c[1]);
                *(float2*)&o[(size_t)(m + 8) * DH + n] = make_float2(c[2], c[3]);
            }
            bar_sync(gen);
        }
        if (bi < BATCH)
            refine_phase(bi, t, t == T_STEPS - 1, b_h, ln_g, ln_b, alpha);
        bar_sync(gen);
    }

    // ---- head GEMM: 8 nt x 8 ks = 64 blocks, B inline from L2 ----
    if (bi < 64) {
        const int nt = bi & 7, ks = bi >> 3;
        __syncthreads();
        a_pack(Ah, Al, g_h, DH, ks * 128);
        __syncthreads();
        float c[4] = {0.f, 0.f, 0.f, 0.f};
        const int n8g = nt * 8 + n8w;
#pragma unroll
        for (int k8 = 0; k8 < 16; k8++) {
            int ai = ((k8 * 4 + mw) * 32 + lane) * 4;
            uint4 ahf = *(const uint4*)&Ah[ai];
            uint4 alf = *(const uint4*)&Al[ai];
            int kg = ks * 128 + k8 * 8;
            uint32_t bh0, bh1, bl0, bl1;
            bfrag(head_W, DH, n8g, kg, lane, bh0, bh1, bl0, bl1);
            mma8(c, ahf, bh0, bh1);
            mma8(c, ahf, bl0, bl1);
            mma8(c, alf, bh0, bh1);
        }
        {
            int m = mw * 16 + gid;
            int n = n8g * 8 + tig * 2;
            float* o = g_hp[ks];
            *(float2*)&o[(size_t)m * DOUT + n] = make_float2(c[0], c[1]);
            *(float2*)&o[(size_t)(m + 8) * DOUT + n] = make_float2(c[2], c[3]);
        }
    }
    bar_sync(gen);

    // ---- loss (blocks 0..63) ----
    if (bi < BATCH) {
        const int o = tid;
        float v0 = 0.f, v1 = 0.f, v2 = 0.f, v3 = 0.f;
        if (o < DOUT) {
            float pred = head_b[o];
#pragma unroll
            for (int s = 0; s < KS; s++) pred += __ldcg(&g_hp[s][bi * DOUT + o]);
            float cc = clean[bi * DOUT + o];
            float d = pred - cc;
            v0 = pred * cc; v1 = pred * pred; v2 = cc * cc; v3 = d * d;
        }
#pragma unroll
        for (int off = 16; off > 0; off >>= 1) {
            v0 += __shfl_down_sync(~0u, v0, off);
            v1 += __shfl_down_sync(~0u, v1, off);
            v2 += __shfl_down_sync(~0u, v2, off);
            v3 += __shfl_down_sync(~0u, v3, off);
        }
        if (lane == 0) {
            red0[warp][0] = v0; red0[warp][1] = v1;
            red0[warp][2] = v2; red0[warp][3] = v3;
        }
        __syncthreads();
        if (warp == 0) {
            if (lane < 4) {
                float s = 0.f;
#pragma unroll 8
                for (int w = 0; w < 32; w++) s += red0[w][lane];
                bcL[lane] = s;
            }
            __syncwarp();
            if (lane == 0) {
                g_lossb[bi] = bcL[3] / (bcL[2] + 1e-6f);
                g_accb[bi]  = bcL[0] / ((sqrtf(bcL[1]) + 1e-6f) *
                                        (sqrtf(bcL[2]) + 1e-6f));
            }
        }
    }
    bar_sync(gen);

    if (bi == 0 && tid < 32) {
        float l = g_lossb[tid] + g_lossb[tid + 32];
        float a = g_accb[tid] + g_accb[tid + 32];
#pragma unroll
        for (int o = 16; o > 0; o >>= 1) {
            l += __shfl_down_sync(~0u, l, o);
            a += __shfl_down_sync(~0u, a, o);
        }
        if (tid == 0) {
            out[0] = l * (1.f / BATCH);
            out[1] = a * (1.f / BATCH);
        }
    }
}

// ---------------- launch ----------------
extern "C" void kernel_launch(void* const* d_in, const int* in_sizes, int n_in,
                              void* d_out, int out_size) {
    const float* z_seq  = (const float*)d_in[0];
    const float* clean  = (const float*)d_in[1];
    const float* W_h    = (const float*)d_in[2];
    const float* W_g    = (const float*)d_in[3];
    const float* b_h    = (const float*)d_in[4];
    const float* ln_g   = (const float*)d_in[5];
    const float* ln_b   = (const float*)d_in[6];
    const float* alpha  = (const float*)d_in[7];
    const float* head_W = (const float*)d_in[8];
    const float* head_b = (const float*)d_in[9];
    float* out = (float*)d_out;

    const int dyn = 32768 * 4;   // 128 KB: A frags (64 KB) + resident W_h frags (64 KB)
    cudaFuncSetAttribute(fused_kernel,
                         cudaFuncAttributeMaxDynamicSharedMemorySize, dyn);
    fused_kernel<<<NBLK, NTHR, dyn>>>(z_seq, clean, W_h, W_g, b_h, ln_g, ln_b,
                                      alpha, head_W, head_b, out);
}